// round 2
// baseline (speedup 1.0000x reference)
#include <cuda_runtime.h>

#define N_NODES 100000
#define N_EDGES 20000
#define NNZ     1600000

// ---------------- scratch (device globals; no allocation allowed) ----------------
__device__ float g_eagg[(size_t)N_EDGES * 300];   // edge-aggregated input feats (max F_in=300)
__device__ float g_ew[(size_t)N_EDGES * 256];     // edge feats after W (max F_out=256)
__device__ float g_h[(size_t)N_NODES * 256];      // node activations (max 256)
__device__ int   g_ecount[N_EDGES];
__device__ int   g_estart[N_EDGES];
__device__ int   g_ecursor[N_EDGES];
__device__ int   g_ncount[N_NODES];
__device__ int   g_nstart[N_NODES];
__device__ int   g_ncursor[N_NODES];
__device__ int   g_csr_e_nodes[NNZ];              // per-edge node lists
__device__ int   g_csr_n_edges[NNZ];              // per-node edge lists
__device__ float g_logits[N_NODES];
__device__ float g_partmax[12500];
__device__ float g_gmax;
__device__ float g_acc[129];                      // [0..127] weighted sum, [128] = Z

// ---------------- init ----------------
__global__ void zero_kernel() {
    int i = blockIdx.x * blockDim.x + threadIdx.x;
    int stride = gridDim.x * blockDim.x;
    for (int j = i; j < N_EDGES; j += stride) g_ecount[j] = 0;
    for (int j = i; j < N_NODES; j += stride) g_ncount[j] = 0;
    if (i < 129) g_acc[i] = 0.0f;
}

// ---------------- degree histograms ----------------
__global__ void hist_kernel(const int* __restrict__ nidx, const int* __restrict__ eidx) {
    int i = blockIdx.x * blockDim.x + threadIdx.x;
    int stride = gridDim.x * blockDim.x;
    for (int j = i; j < NNZ; j += stride) {
        atomicAdd(&g_ecount[eidx[j]], 1);
        atomicAdd(&g_ncount[nidx[j]], 1);
    }
}

// ---------------- single-block exclusive scan over device globals ----------------
// EDGES==1 -> scan g_ecount into g_estart/g_ecursor; EDGES==0 -> node arrays.
// Device code accesses the __device__ globals directly (host-side symbol
// addresses are host shadows on this toolchain -> never pass them as args).
template <int EDGES>
__global__ void scan_kernel() {
    int*       cnt    = EDGES ? g_ecount  : g_ncount;
    int*       start  = EDGES ? g_estart  : g_nstart;
    int*       cursor = EDGES ? g_ecursor : g_ncursor;
    const int  n      = EDGES ? N_EDGES   : N_NODES;

    __shared__ int sh[1024];
    __shared__ int s_carry;
    if (threadIdx.x == 0) s_carry = 0;
    __syncthreads();
    for (int base = 0; base < n; base += 1024) {
        int i = base + threadIdx.x;
        int v = (i < n) ? cnt[i] : 0;
        sh[threadIdx.x] = v;
        __syncthreads();
        for (int off = 1; off < 1024; off <<= 1) {
            int t = 0;
            if (threadIdx.x >= off) t = sh[threadIdx.x - off];
            __syncthreads();
            if (threadIdx.x >= off) sh[threadIdx.x] += t;
            __syncthreads();
        }
        int carry = s_carry;
        int incl = sh[threadIdx.x];
        if (i < n) {
            int excl = carry + incl - v;
            start[i] = excl;
            cursor[i] = excl;
        }
        __syncthreads();
        if (threadIdx.x == 1023) s_carry = carry + sh[1023];
        __syncthreads();
    }
}

// ---------------- CSR scatter ----------------
__global__ void build_csr_kernel(const int* __restrict__ nidx, const int* __restrict__ eidx) {
    int i = blockIdx.x * blockDim.x + threadIdx.x;
    int stride = gridDim.x * blockDim.x;
    for (int j = i; j < NNZ; j += stride) {
        int n = nidx[j];
        int e = eidx[j];
        int p = atomicAdd(&g_ecursor[e], 1);
        g_csr_e_nodes[p] = n;
        int q = atomicAdd(&g_ncursor[n], 1);
        g_csr_n_edges[q] = e;
    }
}

// ---------------- edge aggregation: eagg[e] = mean over nodes of src row ----------------
// one warp per edge; lanes own float4 columns; unroll 4 over node list for MLP
template <int F>
__global__ __launch_bounds__(256) void agg_edge_kernel(const float* __restrict__ src,
                                                       float* __restrict__ dst) {
    constexpr int F4 = F / 4;
    constexpr int V = (F4 + 31) / 32;
    int w = (blockIdx.x * blockDim.x + threadIdx.x) >> 5;
    int lane = threadIdx.x & 31;
    if (w >= N_EDGES) return;
    int s = g_estart[w];
    int cnt = g_ecount[w];
    float4 acc[V];
#pragma unroll
    for (int v = 0; v < V; v++) acc[v] = make_float4(0.f, 0.f, 0.f, 0.f);
    int i = 0;
    for (; i + 4 <= cnt; i += 4) {
        int n0 = g_csr_e_nodes[s + i];
        int n1 = g_csr_e_nodes[s + i + 1];
        int n2 = g_csr_e_nodes[s + i + 2];
        int n3 = g_csr_e_nodes[s + i + 3];
        const float4* r0 = (const float4*)(src + (size_t)n0 * F);
        const float4* r1 = (const float4*)(src + (size_t)n1 * F);
        const float4* r2 = (const float4*)(src + (size_t)n2 * F);
        const float4* r3 = (const float4*)(src + (size_t)n3 * F);
#pragma unroll
        for (int v = 0; v < V; v++) {
            int c = lane + 32 * v;
            if (c < F4) {
                float4 t0 = r0[c], t1 = r1[c], t2 = r2[c], t3 = r3[c];
                acc[v].x += (t0.x + t1.x) + (t2.x + t3.x);
                acc[v].y += (t0.y + t1.y) + (t2.y + t3.y);
                acc[v].z += (t0.z + t1.z) + (t2.z + t3.z);
                acc[v].w += (t0.w + t1.w) + (t2.w + t3.w);
            }
        }
    }
    for (; i < cnt; i++) {
        int n0 = g_csr_e_nodes[s + i];
        const float4* r0 = (const float4*)(src + (size_t)n0 * F);
#pragma unroll
        for (int v = 0; v < V; v++) {
            int c = lane + 32 * v;
            if (c < F4) {
                float4 t0 = r0[c];
                acc[v].x += t0.x; acc[v].y += t0.y; acc[v].z += t0.z; acc[v].w += t0.w;
            }
        }
    }
    float inv = (cnt > 0) ? 1.0f / (float)cnt : 0.0f;
    float4* out = (float4*)(dst + (size_t)w * F);
#pragma unroll
    for (int v = 0; v < V; v++) {
        int c = lane + 32 * v;
        if (c < F4) {
            float4 o;
            o.x = acc[v].x * inv; o.y = acc[v].y * inv;
            o.z = acc[v].z * inv; o.w = acc[v].w * inv;
            out[c] = o;
        }
    }
}

// ---------------- node aggregation: h[n] = act(mean over edges of ew row + bias) ----------------
template <int F, bool LRELU>
__global__ __launch_bounds__(256) void agg_node_kernel(const float* __restrict__ src,
                                                       float* __restrict__ dst,
                                                       const float* __restrict__ bias) {
    constexpr int F4 = F / 4;
    constexpr int V = (F4 + 31) / 32;
    int w = (blockIdx.x * blockDim.x + threadIdx.x) >> 5;
    int lane = threadIdx.x & 31;
    if (w >= N_NODES) return;
    int s = g_nstart[w];
    int cnt = g_ncount[w];
    float4 acc[V];
#pragma unroll
    for (int v = 0; v < V; v++) acc[v] = make_float4(0.f, 0.f, 0.f, 0.f);
    int i = 0;
    for (; i + 4 <= cnt; i += 4) {
        int e0 = g_csr_n_edges[s + i];
        int e1 = g_csr_n_edges[s + i + 1];
        int e2 = g_csr_n_edges[s + i + 2];
        int e3 = g_csr_n_edges[s + i + 3];
        const float4* r0 = (const float4*)(src + (size_t)e0 * F);
        const float4* r1 = (const float4*)(src + (size_t)e1 * F);
        const float4* r2 = (const float4*)(src + (size_t)e2 * F);
        const float4* r3 = (const float4*)(src + (size_t)e3 * F);
#pragma unroll
        for (int v = 0; v < V; v++) {
            int c = lane + 32 * v;
            if (c < F4) {
                float4 t0 = r0[c], t1 = r1[c], t2 = r2[c], t3 = r3[c];
                acc[v].x += (t0.x + t1.x) + (t2.x + t3.x);
                acc[v].y += (t0.y + t1.y) + (t2.y + t3.y);
                acc[v].z += (t0.z + t1.z) + (t2.z + t3.z);
                acc[v].w += (t0.w + t1.w) + (t2.w + t3.w);
            }
        }
    }
    for (; i < cnt; i++) {
        int e0 = g_csr_n_edges[s + i];
        const float4* r0 = (const float4*)(src + (size_t)e0 * F);
#pragma unroll
        for (int v = 0; v < V; v++) {
            int c = lane + 32 * v;
            if (c < F4) {
                float4 t0 = r0[c];
                acc[v].x += t0.x; acc[v].y += t0.y; acc[v].z += t0.z; acc[v].w += t0.w;
            }
        }
    }
    float inv = (cnt > 0) ? 1.0f / (float)cnt : 0.0f;
    const float4* b4 = (const float4*)bias;
    float4* out = (float4*)(dst + (size_t)w * F);
#pragma unroll
    for (int v = 0; v < V; v++) {
        int c = lane + 32 * v;
        if (c < F4) {
            float4 bb = b4[c];
            float4 o;
            o.x = acc[v].x * inv + bb.x;
            o.y = acc[v].y * inv + bb.y;
            o.z = acc[v].z * inv + bb.z;
            o.w = acc[v].w * inv + bb.w;
            if (LRELU) {
                o.x = (o.x > 0.f) ? o.x : 0.01f * o.x;
                o.y = (o.y > 0.f) ? o.y : 0.01f * o.y;
                o.z = (o.z > 0.f) ? o.z : 0.01f * o.z;
                o.w = (o.w > 0.f) ? o.w : 0.01f * o.w;
            }
            out[c] = o;
        }
    }
}

// ---------------- fp32 SGEMM: C[M,N] = A[M,K] @ B[K,N], row-major ----------------
// BM=128, BN=64, BK=8, 256 threads, 8x4 per thread
__global__ __launch_bounds__(256) void sgemm_kernel(const float* __restrict__ A,
                                                    const float* __restrict__ B,
                                                    float* __restrict__ C,
                                                    int M, int K, int N) {
    __shared__ float As[8][136];   // padded: float4-aligned compute reads
    __shared__ float Bs[8][64];
    const int tid = threadIdx.x;
    const int bm = blockIdx.x * 128;
    const int bn = blockIdx.y * 64;
    const int a_row = tid >> 1;            // 0..127
    const int a_col = (tid & 1) * 4;       // 0 or 4
    const int b_row = tid >> 5;            // 0..7
    const int b_col = (tid & 31) * 2;      // 0..62 even
    const int ty = tid >> 4;               // 0..15 -> rows ty*8
    const int tx = tid & 15;               // cols tx*4
    float acc[8][4];
#pragma unroll
    for (int i = 0; i < 8; i++)
#pragma unroll
        for (int j = 0; j < 4; j++) acc[i][j] = 0.f;

    const bool arow_ok = (bm + a_row) < M;
    const float* Ab = A + (size_t)(bm + a_row) * K;

    for (int kt = 0; kt < K; kt += 8) {
#pragma unroll
        for (int j = 0; j < 4; j++) {
            int k = kt + a_col + j;
            As[a_col + j][a_row] = (arow_ok && k < K) ? Ab[k] : 0.f;
        }
        {
            int k = kt + b_row;
            float2 bv = make_float2(0.f, 0.f);
            if (k < K) bv = *(const float2*)(B + (size_t)k * N + bn + b_col);
            *(float2*)&Bs[b_row][b_col] = bv;
        }
        __syncthreads();
#pragma unroll
        for (int k = 0; k < 8; k++) {
            float4 a0 = *(const float4*)&As[k][ty * 8];
            float4 a1 = *(const float4*)&As[k][ty * 8 + 4];
            float4 bv = *(const float4*)&Bs[k][tx * 4];
            float a[8] = {a0.x, a0.y, a0.z, a0.w, a1.x, a1.y, a1.z, a1.w};
            float b[4] = {bv.x, bv.y, bv.z, bv.w};
#pragma unroll
            for (int i = 0; i < 8; i++)
#pragma unroll
                for (int j = 0; j < 4; j++) acc[i][j] += a[i] * b[j];
        }
        __syncthreads();
    }
#pragma unroll
    for (int i = 0; i < 8; i++) {
        int r = bm + ty * 8 + i;
        if (r < M) {
            float4 o = make_float4(acc[i][0], acc[i][1], acc[i][2], acc[i][3]);
            *(float4*)(C + (size_t)r * N + bn + tx * 4) = o;
        }
    }
}

// ---------------- attention epilogue ----------------
__global__ void logits_kernel(const float* __restrict__ h, const float* __restrict__ aw,
                              const float* __restrict__ ab) {
    __shared__ float smax[8];
    int w = (blockIdx.x * blockDim.x + threadIdx.x) >> 5;
    int lane = threadIdx.x & 31;
    float lg = -1e30f;
    if (w < N_NODES) {
        float4 hv = ((const float4*)(h + (size_t)w * 128))[lane];
        float4 wv = ((const float4*)aw)[lane];
        float d = hv.x * wv.x + hv.y * wv.y + hv.z * wv.z + hv.w * wv.w;
#pragma unroll
        for (int off = 16; off > 0; off >>= 1) d += __shfl_xor_sync(0xffffffffu, d, off);
        d += ab[0];
        if (lane == 0) g_logits[w] = d;
        lg = d;
    }
    int wl = threadIdx.x >> 5;
    if (lane == 0) smax[wl] = lg;
    __syncthreads();
    if (threadIdx.x == 0) {
        float m = smax[0];
#pragma unroll
        for (int j = 1; j < 8; j++) m = fmaxf(m, smax[j]);
        g_partmax[blockIdx.x] = m;
    }
}

__global__ void maxred_kernel(int nparts) {
    __shared__ float sm[32];
    float m = -1e30f;
    for (int i = threadIdx.x; i < nparts; i += 1024) m = fmaxf(m, g_partmax[i]);
#pragma unroll
    for (int off = 16; off > 0; off >>= 1) m = fmaxf(m, __shfl_xor_sync(0xffffffffu, m, off));
    if ((threadIdx.x & 31) == 0) sm[threadIdx.x >> 5] = m;
    __syncthreads();
    if (threadIdx.x < 32) {
        float v = sm[threadIdx.x];
#pragma unroll
        for (int off = 16; off > 0; off >>= 1) v = fmaxf(v, __shfl_xor_sync(0xffffffffu, v, off));
        if (threadIdx.x == 0) g_gmax = v;
    }
}

__global__ void accum_kernel(const float* __restrict__ h) {
    int t = threadIdx.x;           // 0..127 feature column
    float gmax = g_gmax;
    int per = (N_NODES + gridDim.x - 1) / gridDim.x;
    int n0 = blockIdx.x * per;
    int n1 = n0 + per;
    if (n1 > N_NODES) n1 = N_NODES;
    float acc = 0.f, z = 0.f;
    for (int n = n0; n < n1; n++) {
        float wgt = expf(g_logits[n] - gmax);
        acc += wgt * h[(size_t)n * 128 + t];
        z += wgt;
    }
    atomicAdd(&g_acc[t], acc);
    if (t == 0) atomicAdd(&g_acc[128], z);
}

__global__ void finalize_kernel(float* __restrict__ out) {
    int t = threadIdx.x;
    out[t] = g_acc[t] / g_acc[128];
}

// ---------------- launch ----------------
extern "C" void kernel_launch(void* const* d_in, const int* in_sizes, int n_in,
                              void* d_out, int out_size) {
    const float* x       = (const float*)d_in[0];          // [100000, 300]
    const int*   nidx    = (const int*)d_in[1];            // hyper_edge_index[0]
    const int*   eidx    = ((const int*)d_in[1]) + NNZ;    // hyper_edge_index[1]
    const float* W1      = (const float*)d_in[2];          // [300,256]
    const float* b1      = (const float*)d_in[3];
    const float* W2      = (const float*)d_in[4];          // [256,256]
    const float* b2      = (const float*)d_in[5];
    const float* W3      = (const float*)d_in[6];          // [256,128]
    const float* b3      = (const float*)d_in[7];
    const float* attn_W  = (const float*)d_in[8];          // [128,1]
    const float* attn_b  = (const float*)d_in[9];          // [1]
    float* out = (float*)d_out;                            // [128]

    // CSR build (reused by all 3 layers)
    zero_kernel<<<512, 256>>>();
    hist_kernel<<<2048, 256>>>(nidx, eidx);
    scan_kernel<1><<<1, 1024>>>();   // edges
    scan_kernel<0><<<1, 1024>>>();   // nodes
    build_csr_kernel<<<2048, 256>>>(nidx, eidx);

    // Layer 1: aggregate x (F=300) to edges, GEMM at edges, spread to nodes (F=256), lrelu
    agg_edge_kernel<300><<<2500, 256>>>(x, g_eagg);
    sgemm_kernel<<<dim3(157, 4), 256>>>(g_eagg, W1, g_ew, N_EDGES, 300, 256);
    agg_node_kernel<256, true><<<12500, 256>>>(g_ew, g_h, b1);

    // Layer 2
    agg_edge_kernel<256><<<2500, 256>>>(g_h, g_eagg);
    sgemm_kernel<<<dim3(157, 4), 256>>>(g_eagg, W2, g_ew, N_EDGES, 256, 256);
    agg_node_kernel<256, true><<<12500, 256>>>(g_ew, g_h, b2);

    // Layer 3 (no activation)
    agg_edge_kernel<256><<<2500, 256>>>(g_h, g_eagg);
    sgemm_kernel<<<dim3(157, 2), 256>>>(g_eagg, W3, g_ew, N_EDGES, 256, 128);
    agg_node_kernel<128, false><<<12500, 256>>>(g_ew, g_h, b3);

    // Attention pooling (softmax over nodes, weighted sum -> [128])
    logits_kernel<<<12500, 256>>>(g_h, attn_W, attn_b);
    maxred_kernel<<<1, 1024>>>(12500);
    accum_kernel<<<512, 128>>>(g_h);
    finalize_kernel<<<1, 128>>>(out);
}